// round 12
// baseline (speedup 1.0000x reference)
#include <cuda_runtime.h>
#include <cuda_fp16.h>
#include <stdint.h>

#define MAX_NODES 100000
#define MAX_EDGES 1600000
#define D 128

typedef unsigned long long ull;

// ---- device scratch ----
__device__ __align__(256) int   g_deg[MAX_NODES];
__device__ __align__(256) int   g_off[MAX_NODES + 1];
__device__ __align__(256) int   g_cur[MAX_NODES];
__device__ __align__(256) unsigned int g_ready[128];
__device__ __align__(256) ull   g_pairs[MAX_EDGES];    // (wt<<32 | src*512)
__device__ __align__(256) float g_agg[(size_t)MAX_NODES * D];

// ---------------------------------------------------------------------------
__global__ void count_kernel(const int* __restrict__ ei, int E, int N) {
    int e4 = blockIdx.x * blockDim.x + threadIdx.x;
    int base = e4 * 4;
    if (base + 4 <= E) {
        int4 d = *(const int4*)(ei + E + base);
        if ((unsigned)d.x < (unsigned)N) atomicAdd(&g_deg[d.x], 1);
        if ((unsigned)d.y < (unsigned)N) atomicAdd(&g_deg[d.y], 1);
        if ((unsigned)d.z < (unsigned)N) atomicAdd(&g_deg[d.z], 1);
        if ((unsigned)d.w < (unsigned)N) atomicAdd(&g_deg[d.w], 1);
    } else {
        for (int e = base; e < E; e++) {
            int dst = ei[E + e];
            if ((unsigned)dst < (unsigned)N) atomicAdd(&g_deg[dst], 1);
        }
    }
}

// Single-kernel scan: per-block scan + publish + parallel lookback.
__global__ __launch_bounds__(1024) void scan_kernel(int n, int nb) {
    __shared__ int warp_sums[32];
    __shared__ int s_carry;
    const int tid  = threadIdx.x;
    const int lane = tid & 31;
    const int wid  = tid >> 5;
    const int bid  = blockIdx.x;
    const int i    = bid * 1024 + tid;

    int v = (i < n) ? g_deg[i] : 0;
    int incl = v;
    #pragma unroll
    for (int d = 1; d < 32; d <<= 1) {
        int t = __shfl_up_sync(0xFFFFFFFFu, incl, d);
        if (lane >= d) incl += t;
    }
    if (lane == 31) warp_sums[wid] = incl;
    __syncthreads();
    if (wid == 0) {
        int wv = warp_sums[lane];
        #pragma unroll
        for (int d = 1; d < 32; d <<= 1) {
            int t = __shfl_up_sync(0xFFFFFFFFu, wv, d);
            if (lane >= d) wv += t;
        }
        warp_sums[lane] = wv;
    }
    __syncthreads();
    const int block_total = warp_sums[31];

    if (tid == 0)
        atomicExch(&g_ready[bid], 0x80000000u | (unsigned)block_total);

    if (wid == 0) {
        unsigned carry = 0;
        bool done = (bid == 0);
        while (!done) {
            unsigned sum = 0;
            bool ok = true;
            for (int j = lane; j < bid; j += 32) {
                unsigned r = *((volatile unsigned*)&g_ready[j]);
                if (!(r & 0x80000000u)) ok = false;
                else sum += r & 0x7FFFFFFFu;
            }
            if (__all_sync(0xFFFFFFFFu, ok)) {
                #pragma unroll
                for (int d = 16; d > 0; d >>= 1)
                    sum += __shfl_down_sync(0xFFFFFFFFu, sum, d);
                carry = sum;
                done = true;
            }
        }
        if (lane == 0) s_carry = (int)carry;
    }
    __syncthreads();

    int base = s_carry + ((wid > 0) ? warp_sums[wid - 1] : 0);
    if (i < n) {
        int ex = base + incl - v;
        g_off[i] = ex;
        g_cur[i] = ex;
    }
    if (bid == nb - 1 && tid == 0) g_off[n] = s_carry + block_total;
}

__global__ void fill_kernel(const int* __restrict__ ei,
                            const float* __restrict__ ew, int E, int N) {
    int e = blockIdx.x * blockDim.x + threadIdx.x;
    if (e < E) {
        int src = ei[e];
        int dst = ei[E + e];
        if ((unsigned)dst < (unsigned)N && (unsigned)src < (unsigned)N) {
            int pos = atomicAdd(&g_cur[dst], 1);
            // low word = pre-scaled row byte offset (src * 512 bytes)
            g_pairs[pos] = ((ull)__float_as_uint(ew[e]) << 32)
                         | ((unsigned)src << 9);
        }
    }
}

__device__ __forceinline__ ull dup_hi(ull p) {
    ull r;
    unsigned hi = (unsigned)(p >> 32);
    asm("mov.b64 %0, {%1, %2};" : "=l"(r) : "r"(hi), "r"(hi));
    return r;
}

__device__ __forceinline__ void fma_x2(ull& acc, ull a, ull w) {
    asm("fma.rn.f32x2 %0, %1, %2, %0;" : "+l"(acc) : "l"(a), "l"(w));
}

// One warp per node; 4-deep gather, pre-scaled offsets, f32x2 accumulate.
__global__ void aggregate_kernel(const float* __restrict__ x, int n) {
    int gw   = (blockIdx.x * blockDim.x + threadIdx.x) >> 5;
    int lane = threadIdx.x & 31;
    if (gw >= n) return;
    const char* xb = (const char*)x + lane * 16;   // lane's 16B slice base
    int i   = g_off[gw];
    int end = g_off[gw + 1];
    ull accA0 = 0, accB0 = 0, accA1 = 0, accB1 = 0;
    ull accA2 = 0, accB2 = 0, accA3 = 0, accB3 = 0;
    for (; i + 4 <= end; i += 4) {
        ull p0 = g_pairs[i],     p1 = g_pairs[i + 1];
        ull p2 = g_pairs[i + 2], p3 = g_pairs[i + 3];
        ulonglong2 v0 = *(const ulonglong2*)(xb + (unsigned)p0);
        ulonglong2 v1 = *(const ulonglong2*)(xb + (unsigned)p1);
        ulonglong2 v2 = *(const ulonglong2*)(xb + (unsigned)p2);
        ulonglong2 v3 = *(const ulonglong2*)(xb + (unsigned)p3);
        ull w0 = dup_hi(p0), w1 = dup_hi(p1);
        ull w2 = dup_hi(p2), w3 = dup_hi(p3);
        fma_x2(accA0, v0.x, w0); fma_x2(accB0, v0.y, w0);
        fma_x2(accA1, v1.x, w1); fma_x2(accB1, v1.y, w1);
        fma_x2(accA2, v2.x, w2); fma_x2(accB2, v2.y, w2);
        fma_x2(accA3, v3.x, w3); fma_x2(accB3, v3.y, w3);
    }
    for (; i < end; i++) {
        ull p = g_pairs[i];
        ulonglong2 v = *(const ulonglong2*)(xb + (unsigned)p);
        ull w = dup_hi(p);
        fma_x2(accA0, v.x, w); fma_x2(accB0, v.y, w);
    }
    // reduce 4 accumulator sets (packed) then unpack
    fma_x2(accA0, accA1, 0x3F8000003F800000ULL);   // accA0 += accA1 * 1.0f
    fma_x2(accB0, accB1, 0x3F8000003F800000ULL);
    fma_x2(accA2, accA3, 0x3F8000003F800000ULL);
    fma_x2(accB2, accB3, 0x3F8000003F800000ULL);
    fma_x2(accA0, accA2, 0x3F8000003F800000ULL);
    fma_x2(accB0, accB2, 0x3F8000003F800000ULL);
    ulonglong2 r;
    r.x = accA0; r.y = accB0;
    *(ulonglong2*)(g_agg + (size_t)gw * D + lane * 4) = r;
}

// ============================================================================
// HMMA GEMM (identical to round-10): mma.sync m16n8k16 f16->f32.
// ============================================================================

#define SH_STRIDE 136

__device__ __forceinline__ uint32_t smem_u32(const void* p) {
    return (uint32_t)__cvta_generic_to_shared(p);
}

__device__ __forceinline__ void ldsm_x4(uint32_t& r0, uint32_t& r1,
                                        uint32_t& r2, uint32_t& r3, uint32_t a) {
    asm volatile("ldmatrix.sync.aligned.m8n8.x4.shared.b16 {%0,%1,%2,%3}, [%4];"
                 : "=r"(r0), "=r"(r1), "=r"(r2), "=r"(r3) : "r"(a));
}

__device__ __forceinline__ void hmma(float& c0, float& c1, float& c2, float& c3,
                                     uint32_t a0, uint32_t a1, uint32_t a2, uint32_t a3,
                                     uint32_t b0, uint32_t b1) {
    asm volatile("mma.sync.aligned.m16n8k16.row.col.f32.f16.f16.f32 "
                 "{%0,%1,%2,%3}, {%4,%5,%6,%7}, {%8,%9}, {%0,%1,%2,%3};"
                 : "+f"(c0), "+f"(c1), "+f"(c2), "+f"(c3)
                 : "r"(a0), "r"(a1), "r"(a2), "r"(a3), "r"(b0), "r"(b1));
}

#define GEMM_SMEM (2 * 128 * SH_STRIDE * 2)

__global__ __launch_bounds__(256) void gemm_hmma_kernel(const float* __restrict__ W,
                                                        const float* __restrict__ b,
                                                        float* __restrict__ out, int M) {
    extern __shared__ __align__(16) __half sh[];
    __half* sA = sh;
    __half* sW = sh + 128 * SH_STRIDE;
    const int tid  = threadIdx.x;
    const int wid  = tid >> 5;
    const int lane = tid & 31;
    const int mb   = blockIdx.x * 128;

    for (int idx = tid; idx < 128 * 32; idx += 256) {
        int r = idx >> 5, c4 = idx & 31;
        float4 v = ((const float4*)(W + r * 128))[c4];
        *(__half2*)&sW[r * SH_STRIDE + c4 * 4]     = __floats2half2_rn(v.x, v.y);
        *(__half2*)&sW[r * SH_STRIDE + c4 * 4 + 2] = __floats2half2_rn(v.z, v.w);
    }
    for (int idx = tid; idx < 128 * 32; idx += 256) {
        int r = idx >> 5, c4 = idx & 31;
        int row = mb + r;
        float4 v = (row < M) ? ((const float4*)(g_agg + (size_t)row * 128))[c4]
                             : make_float4(0.f, 0.f, 0.f, 0.f);
        *(__half2*)&sA[r * SH_STRIDE + c4 * 4]     = __floats2half2_rn(v.x, v.y);
        *(__half2*)&sA[r * SH_STRIDE + c4 * 4 + 2] = __floats2half2_rn(v.z, v.w);
    }
    __syncthreads();

    const int m0 = (wid & 3) * 32;
    const int n0 = (wid >> 2) * 64;

    float acc[2][8][4];
    #pragma unroll
    for (int i = 0; i < 2; i++)
        #pragma unroll
        for (int j = 0; j < 8; j++)
            #pragma unroll
            for (int q = 0; q < 4; q++) acc[i][j][q] = 0.f;

    const int a_row_off = lane & 15;
    const int a_col_off = (lane >> 4) * 8;
    const int b_row_off = (lane & 7) + ((lane >> 4) & 1) * 8;
    const int b_col_off = ((lane >> 3) & 1) * 8;

    #pragma unroll
    for (int kt = 0; kt < 8; kt++) {
        const int klo = kt * 16;
        uint32_t af[2][4];
        #pragma unroll
        for (int mf = 0; mf < 2; mf++) {
            uint32_t addr = smem_u32(&sA[(m0 + mf * 16 + a_row_off) * SH_STRIDE
                                         + klo + a_col_off]);
            ldsm_x4(af[mf][0], af[mf][1], af[mf][2], af[mf][3], addr);
        }
        uint32_t bf[8][2];
        #pragma unroll
        for (int g = 0; g < 4; g++) {
            uint32_t r0, r1, r2, r3;
            uint32_t addr = smem_u32(&sW[(n0 + g * 16 + b_row_off) * SH_STRIDE
                                         + klo + b_col_off]);
            ldsm_x4(r0, r1, r2, r3, addr);
            bf[g * 2][0] = r0; bf[g * 2][1] = r1;
            bf[g * 2 + 1][0] = r2; bf[g * 2 + 1][1] = r3;
        }
        #pragma unroll
        for (int mf = 0; mf < 2; mf++)
            #pragma unroll
            for (int nf = 0; nf < 8; nf++)
                hmma(acc[mf][nf][0], acc[mf][nf][1], acc[mf][nf][2], acc[mf][nf][3],
                     af[mf][0], af[mf][1], af[mf][2], af[mf][3],
                     bf[nf][0], bf[nf][1]);
    }

    const int tq = lane >> 2;
    const int tc = (lane & 3) * 2;
    #pragma unroll
    for (int nf = 0; nf < 8; nf++) {
        int col = n0 + nf * 8 + tc;
        float2 bv = *(const float2*)&b[col];
        #pragma unroll
        for (int mf = 0; mf < 2; mf++) {
            int r0 = mb + m0 + mf * 16 + tq;
            int r1 = r0 + 8;
            if (r0 < M) {
                float2 o = make_float2(acc[mf][nf][0] + bv.x, acc[mf][nf][1] + bv.y);
                *(float2*)&out[(size_t)r0 * 128 + col] = o;
            }
            if (r1 < M) {
                float2 o = make_float2(acc[mf][nf][2] + bv.x, acc[mf][nf][3] + bv.y);
                *(float2*)&out[(size_t)r1 * 128 + col] = o;
            }
        }
    }
}

// ---------------------------------------------------------------------------
extern "C" void kernel_launch(void* const* d_in, const int* in_sizes, int n_in,
                              void* d_out, int out_size) {
    const float* x  = (const float*)d_in[0];
    const int*   ei = (const int*)d_in[1];
    const float* ew = (const float*)d_in[2];
    const float* W  = (const float*)d_in[3];
    const float* b  = (const float*)d_in[4];
    float*       out = (float*)d_out;

    int N = in_sizes[0] / D;      // 100000
    int E = in_sizes[2];          // 1600000
    int nb = (N + 1023) / 1024;   // 98
    int e4 = (E + 3) / 4;

    void* p_deg = nullptr; void* p_rdy = nullptr;
    cudaGetSymbolAddress(&p_deg, g_deg);
    cudaGetSymbolAddress(&p_rdy, g_ready);
    cudaMemsetAsync(p_deg, 0, (size_t)N * sizeof(int));
    cudaMemsetAsync(p_rdy, 0, 128 * sizeof(unsigned int));

    count_kernel<<<(e4 + 255) / 256, 256>>>(ei, E, N);              // launch 0
    scan_kernel<<<nb, 1024>>>(N, nb);                               // launch 1
    fill_kernel<<<(E + 255) / 256, 256>>>(ei, ew, E, N);            // launch 2
    aggregate_kernel<<<((size_t)N * 32 + 255) / 256, 256>>>(x, N);  // launch 3
    cudaFuncSetAttribute(gemm_hmma_kernel,
                         cudaFuncAttributeMaxDynamicSharedMemorySize, GEMM_SMEM);
    gemm_hmma_kernel<<<(N + 127) / 128, 256, GEMM_SMEM>>>(W, b, out, N);
}

// round 13
// speedup vs baseline: 1.1123x; 1.1123x over previous
#include <cuda_runtime.h>
#include <cuda_fp16.h>
#include <stdint.h>

#define MAX_NODES 100000
#define MAX_EDGES 1600000
#define D 128

typedef unsigned long long ull;

// ---- device scratch ----
__device__ __align__(256) int   g_deg[MAX_NODES];
__device__ __align__(256) int   g_off[MAX_NODES + 1];
__device__ __align__(256) int   g_cur[MAX_NODES];
__device__ __align__(256) unsigned int g_ready[128];
__device__ __align__(256) ull   g_pairs[MAX_EDGES];    // (wt<<32 | src*512)
__device__ __align__(256) float g_agg[(size_t)MAX_NODES * D];

// ---------------------------------------------------------------------------
__global__ void count_kernel(const int* __restrict__ ei, int E, int N) {
    int e4 = blockIdx.x * blockDim.x + threadIdx.x;
    int base = e4 * 4;
    if (base + 4 <= E) {
        int4 d = *(const int4*)(ei + E + base);
        if ((unsigned)d.x < (unsigned)N) atomicAdd(&g_deg[d.x], 1);
        if ((unsigned)d.y < (unsigned)N) atomicAdd(&g_deg[d.y], 1);
        if ((unsigned)d.z < (unsigned)N) atomicAdd(&g_deg[d.z], 1);
        if ((unsigned)d.w < (unsigned)N) atomicAdd(&g_deg[d.w], 1);
    } else {
        for (int e = base; e < E; e++) {
            int dst = ei[E + e];
            if ((unsigned)dst < (unsigned)N) atomicAdd(&g_deg[dst], 1);
        }
    }
}

// Single-kernel scan: per-block scan + publish + parallel lookback.
__global__ __launch_bounds__(1024) void scan_kernel(int n, int nb) {
    __shared__ int warp_sums[32];
    __shared__ int s_carry;
    const int tid  = threadIdx.x;
    const int lane = tid & 31;
    const int wid  = tid >> 5;
    const int bid  = blockIdx.x;
    const int i    = bid * 1024 + tid;

    int v = (i < n) ? g_deg[i] : 0;
    int incl = v;
    #pragma unroll
    for (int d = 1; d < 32; d <<= 1) {
        int t = __shfl_up_sync(0xFFFFFFFFu, incl, d);
        if (lane >= d) incl += t;
    }
    if (lane == 31) warp_sums[wid] = incl;
    __syncthreads();
    if (wid == 0) {
        int wv = warp_sums[lane];
        #pragma unroll
        for (int d = 1; d < 32; d <<= 1) {
            int t = __shfl_up_sync(0xFFFFFFFFu, wv, d);
            if (lane >= d) wv += t;
        }
        warp_sums[lane] = wv;
    }
    __syncthreads();
    const int block_total = warp_sums[31];

    if (tid == 0)
        atomicExch(&g_ready[bid], 0x80000000u | (unsigned)block_total);

    if (wid == 0) {
        unsigned carry = 0;
        bool done = (bid == 0);
        while (!done) {
            unsigned sum = 0;
            bool ok = true;
            for (int j = lane; j < bid; j += 32) {
                unsigned r = *((volatile unsigned*)&g_ready[j]);
                if (!(r & 0x80000000u)) ok = false;
                else sum += r & 0x7FFFFFFFu;
            }
            if (__all_sync(0xFFFFFFFFu, ok)) {
                #pragma unroll
                for (int d = 16; d > 0; d >>= 1)
                    sum += __shfl_down_sync(0xFFFFFFFFu, sum, d);
                carry = sum;
                done = true;
            }
        }
        if (lane == 0) s_carry = (int)carry;
    }
    __syncthreads();

    int base = s_carry + ((wid > 0) ? warp_sums[wid - 1] : 0);
    if (i < n) {
        int ex = base + incl - v;
        g_off[i] = ex;
        g_cur[i] = ex;
    }
    if (bid == nb - 1 && tid == 0) g_off[n] = s_carry + block_total;
}

__global__ void fill_kernel(const int* __restrict__ ei,
                            const float* __restrict__ ew, int E, int N) {
    int e = blockIdx.x * blockDim.x + threadIdx.x;
    if (e < E) {
        int src = ei[e];
        int dst = ei[E + e];
        if ((unsigned)dst < (unsigned)N && (unsigned)src < (unsigned)N) {
            int pos = atomicAdd(&g_cur[dst], 1);
            // low word = pre-scaled row byte offset (src * 512 bytes)
            g_pairs[pos] = ((ull)__float_as_uint(ew[e]) << 32)
                         | ((unsigned)src << 9);
        }
    }
}

// One warp per node; 2-deep gather with pre-scaled byte offsets, scalar fp32
// FMAs. Register-dieted (<=32 regs) so 8 blocks/SM co-reside -> 64 warps/SM.
__global__ __launch_bounds__(256, 8)
void aggregate_kernel(const float* __restrict__ x, int n) {
    int gw   = (blockIdx.x * blockDim.x + threadIdx.x) >> 5;
    int lane = threadIdx.x & 31;
    if (gw >= n) return;
    const char* xb = (const char*)x + lane * 16;   // lane's 16B slice base
    int i   = g_off[gw];
    int end = g_off[gw + 1];
    float4 a0 = make_float4(0.f, 0.f, 0.f, 0.f);
    float4 a1 = make_float4(0.f, 0.f, 0.f, 0.f);
    for (; i + 2 <= end; i += 2) {
        ull p0 = g_pairs[i];
        ull p1 = g_pairs[i + 1];
        float4 v0 = *(const float4*)(xb + (unsigned)p0);
        float4 v1 = *(const float4*)(xb + (unsigned)p1);
        float w0 = __uint_as_float((unsigned)(p0 >> 32));
        float w1 = __uint_as_float((unsigned)(p1 >> 32));
        a0.x += w0 * v0.x; a0.y += w0 * v0.y; a0.z += w0 * v0.z; a0.w += w0 * v0.w;
        a1.x += w1 * v1.x; a1.y += w1 * v1.y; a1.z += w1 * v1.z; a1.w += w1 * v1.w;
    }
    if (i < end) {
        ull p = g_pairs[i];
        float4 v = *(const float4*)(xb + (unsigned)p);
        float w = __uint_as_float((unsigned)(p >> 32));
        a0.x += w * v.x; a0.y += w * v.y; a0.z += w * v.z; a0.w += w * v.w;
    }
    float4 r = make_float4(a0.x + a1.x, a0.y + a1.y, a0.z + a1.z, a0.w + a1.w);
    *(float4*)(g_agg + (size_t)gw * D + lane * 4) = r;
}

// ============================================================================
// HMMA GEMM (identical to round-10): mma.sync m16n8k16 f16->f32.
// ============================================================================

#define SH_STRIDE 136

__device__ __forceinline__ uint32_t smem_u32(const void* p) {
    return (uint32_t)__cvta_generic_to_shared(p);
}

__device__ __forceinline__ void ldsm_x4(uint32_t& r0, uint32_t& r1,
                                        uint32_t& r2, uint32_t& r3, uint32_t a) {
    asm volatile("ldmatrix.sync.aligned.m8n8.x4.shared.b16 {%0,%1,%2,%3}, [%4];"
                 : "=r"(r0), "=r"(r1), "=r"(r2), "=r"(r3) : "r"(a));
}

__device__ __forceinline__ void hmma(float& c0, float& c1, float& c2, float& c3,
                                     uint32_t a0, uint32_t a1, uint32_t a2, uint32_t a3,
                                     uint32_t b0, uint32_t b1) {
    asm volatile("mma.sync.aligned.m16n8k16.row.col.f32.f16.f16.f32 "
                 "{%0,%1,%2,%3}, {%4,%5,%6,%7}, {%8,%9}, {%0,%1,%2,%3};"
                 : "+f"(c0), "+f"(c1), "+f"(c2), "+f"(c3)
                 : "r"(a0), "r"(a1), "r"(a2), "r"(a3), "r"(b0), "r"(b1));
}

#define GEMM_SMEM (2 * 128 * SH_STRIDE * 2)

__global__ __launch_bounds__(256) void gemm_hmma_kernel(const float* __restrict__ W,
                                                        const float* __restrict__ b,
                                                        float* __restrict__ out, int M) {
    extern __shared__ __align__(16) __half sh[];
    __half* sA = sh;
    __half* sW = sh + 128 * SH_STRIDE;
    const int tid  = threadIdx.x;
    const int wid  = tid >> 5;
    const int lane = tid & 31;
    const int mb   = blockIdx.x * 128;

    for (int idx = tid; idx < 128 * 32; idx += 256) {
        int r = idx >> 5, c4 = idx & 31;
        float4 v = ((const float4*)(W + r * 128))[c4];
        *(__half2*)&sW[r * SH_STRIDE + c4 * 4]     = __floats2half2_rn(v.x, v.y);
        *(__half2*)&sW[r * SH_STRIDE + c4 * 4 + 2] = __floats2half2_rn(v.z, v.w);
    }
    for (int idx = tid; idx < 128 * 32; idx += 256) {
        int r = idx >> 5, c4 = idx & 31;
        int row = mb + r;
        float4 v = (row < M) ? ((const float4*)(g_agg + (size_t)row * 128))[c4]
                             : make_float4(0.f, 0.f, 0.f, 0.f);
        *(__half2*)&sA[r * SH_STRIDE + c4 * 4]     = __floats2half2_rn(v.x, v.y);
        *(__half2*)&sA[r * SH_STRIDE + c4 * 4 + 2] = __floats2half2_rn(v.z, v.w);
    }
    __syncthreads();

    const int m0 = (wid & 3) * 32;
    const int n0 = (wid >> 2) * 64;

    float acc[2][8][4];
    #pragma unroll
    for (int i = 0; i < 2; i++)
        #pragma unroll
        for (int j = 0; j < 8; j++)
            #pragma unroll
            for (int q = 0; q < 4; q++) acc[i][j][q] = 0.f;

    const int a_row_off = lane & 15;
    const int a_col_off = (lane >> 4) * 8;
    const int b_row_off = (lane & 7) + ((lane >> 4) & 1) * 8;
    const int b_col_off = ((lane >> 3) & 1) * 8;

    #pragma unroll
    for (int kt = 0; kt < 8; kt++) {
        const int klo = kt * 16;
        uint32_t af[2][4];
        #pragma unroll
        for (int mf = 0; mf < 2; mf++) {
            uint32_t addr = smem_u32(&sA[(m0 + mf * 16 + a_row_off) * SH_STRIDE
                                         + klo + a_col_off]);
            ldsm_x4(af[mf][0], af[mf][1], af[mf][2], af[mf][3], addr);
        }
        uint32_t bf[8][2];
        #pragma unroll
        for (int g = 0; g < 4; g++) {
            uint32_t r0, r1, r2, r3;
            uint32_t addr = smem_u32(&sW[(n0 + g * 16 + b_row_off) * SH_STRIDE
                                         + klo + b_col_off]);
            ldsm_x4(r0, r1, r2, r3, addr);
            bf[g * 2][0] = r0; bf[g * 2][1] = r1;
            bf[g * 2 + 1][0] = r2; bf[g * 2 + 1][1] = r3;
        }
        #pragma unroll
        for (int mf = 0; mf < 2; mf++)
            #pragma unroll
            for (int nf = 0; nf < 8; nf++)
                hmma(acc[mf][nf][0], acc[mf][nf][1], acc[mf][nf][2], acc[mf][nf][3],
                     af[mf][0], af[mf][1], af[mf][2], af[mf][3],
                     bf[nf][0], bf[nf][1]);
    }

    const int tq = lane >> 2;
    const int tc = (lane & 3) * 2;
    #pragma unroll
    for (int nf = 0; nf < 8; nf++) {
        int col = n0 + nf * 8 + tc;
        float2 bv = *(const float2*)&b[col];
        #pragma unroll
        for (int mf = 0; mf < 2; mf++) {
            int r0 = mb + m0 + mf * 16 + tq;
            int r1 = r0 + 8;
            if (r0 < M) {
                float2 o = make_float2(acc[mf][nf][0] + bv.x, acc[mf][nf][1] + bv.y);
                *(float2*)&out[(size_t)r0 * 128 + col] = o;
            }
            if (r1 < M) {
                float2 o = make_float2(acc[mf][nf][2] + bv.x, acc[mf][nf][3] + bv.y);
                *(float2*)&out[(size_t)r1 * 128 + col] = o;
            }
        }
    }
}

// ---------------------------------------------------------------------------
extern "C" void kernel_launch(void* const* d_in, const int* in_sizes, int n_in,
                              void* d_out, int out_size) {
    const float* x  = (const float*)d_in[0];
    const int*   ei = (const int*)d_in[1];
    const float* ew = (const float*)d_in[2];
    const float* W  = (const float*)d_in[3];
    const float* b  = (const float*)d_in[4];
    float*       out = (float*)d_out;

    int N = in_sizes[0] / D;      // 100000
    int E = in_sizes[2];          // 1600000
    int nb = (N + 1023) / 1024;   // 98
    int e4 = (E + 3) / 4;

    void* p_deg = nullptr; void* p_rdy = nullptr;
    cudaGetSymbolAddress(&p_deg, g_deg);
    cudaGetSymbolAddress(&p_rdy, g_ready);
    cudaMemsetAsync(p_deg, 0, (size_t)N * sizeof(int));
    cudaMemsetAsync(p_rdy, 0, 128 * sizeof(unsigned int));

    count_kernel<<<(e4 + 255) / 256, 256>>>(ei, E, N);              // launch 0
    scan_kernel<<<nb, 1024>>>(N, nb);                               // launch 1
    fill_kernel<<<(E + 255) / 256, 256>>>(ei, ew, E, N);            // launch 2
    aggregate_kernel<<<((size_t)N * 32 + 255) / 256, 256>>>(x, N);  // launch 3
    cudaFuncSetAttribute(gemm_hmma_kernel,
                         cudaFuncAttributeMaxDynamicSharedMemorySize, GEMM_SMEM);
    gemm_hmma_kernel<<<(N + 127) / 128, 256, GEMM_SMEM>>>(W, b, out, N);
}